// round 14
// baseline (speedup 1.0000x reference)
#include <cuda_runtime.h>
#include <cuda_fp16.h>
#include <cstdint>

#define TTOK  16384
#define DDIM  4096
#define NEXP  64
#define MROWS 64                // tokens per CTA
#define KC    64                // k per chunk
#define NCH   (DDIM / KC)       // 64 chunks
#define NTH   256

#define SWZ(x) ((x) ^ (((x) >> 3) & 0x70))

// smem: 3-stage ring; per stage A 2 planes x 8KB + B 2 planes x 8KB
#define A_PLANE 8192
#define A_STAGE 16384
#define B_PLANE 8192
#define B_STAGE 16384
#define SOFF_A  0
#define SOFF_B  (3 * A_STAGE)               // 49152
#define SMEM_TOTAL (SOFF_B + 3 * B_STAGE)   // 98304

#define LO_SCALE   2048.0f
#define LO_INV     4.8828125e-4f            // 1/2048

// named barriers: ready[s] = 1+s (producer->consumer), free[s] = 4+s (consumer->producer)
#define BAR_SYNC(id)   asm volatile("bar.sync %0, 256;"   :: "r"(id) : "memory")
#define BAR_ARRIVE(id) asm volatile("bar.arrive %0, 256;" :: "r"(id) : "memory")
#define MEMBAR_CTA()   asm volatile("membar.cta;" ::: "memory")

// W pre-split planes, swizzled tile layout: [kc][plane(2)][2048 u32] (16KB/chunk)
__device__ __align__(16) uint32_t gWs[NCH * 2 * 2048];

// ---- fp16 2-way split of two floats; lo pre-scaled by 2048 ----
__device__ __forceinline__ void split2h(float x0, float x1,
                                        uint32_t& whi, uint32_t& wlo) {
    __half2 hh = __float22half2_rn(make_float2(x0, x1));
    float2 back = __half22float2(hh);
    float r0 = (x0 - back.x) * LO_SCALE;
    float r1 = (x1 - back.y) * LO_SCALE;
    __half2 ll = __float22half2_rn(make_float2(r0, r1));
    whi = *(uint32_t*)&hh;
    wlo = *(uint32_t*)&ll;
}

__device__ __forceinline__ uint32_t s2u(const void* p) {
    uint32_t a;
    asm("{ .reg .u64 t; cvta.to.shared.u64 t, %1; cvt.u32.u64 %0, t; }" : "=r"(a) : "l"(p));
    return a;
}

__device__ __forceinline__ void ldm4(uint32_t* r, uint32_t addr) {
    asm volatile("ldmatrix.sync.aligned.m8n8.x4.shared.b16 {%0,%1,%2,%3}, [%4];"
                 : "=r"(r[0]), "=r"(r[1]), "=r"(r[2]), "=r"(r[3]) : "r"(addr));
}

__device__ __forceinline__ void mma16816(float* d, const uint32_t* a,
                                         uint32_t b0, uint32_t b1) {
    asm volatile("mma.sync.aligned.m16n8k16.row.col.f32.f16.f16.f32 "
                 "{%0,%1,%2,%3}, {%4,%5,%6,%7}, {%8,%9}, {%0,%1,%2,%3};"
                 : "+f"(d[0]), "+f"(d[1]), "+f"(d[2]), "+f"(d[3])
                 : "r"(a[0]), "r"(a[1]), "r"(a[2]), "r"(a[3]), "r"(b0), "r"(b1));
}

// ---- kernel 0: split W once into swizzled fp16 plane tiles ----
__global__ __launch_bounds__(256)
void split_w_kernel(const float* __restrict__ W) {
    const int j = blockIdx.x * 256 + threadIdx.x;   // pair index, 0..131071
    const int e  = j >> 11;                          // expert 0..63
    const int k0 = (j & 2047) << 1;                  // even k
    float x0 = W[e * DDIM + k0];
    float x1 = W[e * DDIM + k0 + 1];
    uint32_t whi, wlo;
    split2h(x0, x1, whi, wlo);
    const int kc  = k0 >> 6;
    const int off = SWZ(e * 128 + (k0 & 63) * 2) >> 2;   // u32 index in tile
    gWs[(kc * 2 + 0) * 2048 + off] = whi;
    gWs[(kc * 2 + 1) * 2048 + off] = wlo;
}

// ---- main: warp-specialized; producer keeps A+B in regs, no async waits ----
__global__ __launch_bounds__(NTH, 2)
void gate_kernel(const float* __restrict__ h, float* __restrict__ out)
{
    extern __shared__ __align__(16) char smem[];
    const uint32_t sbase = s2u(smem);
    const int tid = threadIdx.x;
    const int wid = tid >> 5;
    const int lid = tid & 31;

    const float* hblk = h + (size_t)blockIdx.x * MROWS * DDIM;
    const uint4* gw = (const uint4*)gWs;   // 1024 uint4 per chunk

    const bool is_prod = (wid >= 4);

    if (!is_prod) {
        // ================= CONSUMER: pure ldmatrix + MMA =================
        float accH[2][4][4], accL[2][4][4];
#pragma unroll
        for (int mt = 0; mt < 2; mt++)
#pragma unroll
            for (int f = 0; f < 4; f++)
#pragma unroll
                for (int c = 0; c < 4; c++) { accH[mt][f][c] = 0.f; accL[mt][f][c] = 0.f; }

        const int mbase = (wid & 1) << 5;
        const int nbase = ((wid >> 1) & 1) << 5;
        const int arow0 = mbase + (lid & 15);
        const int ax    = (lid >> 4) << 4;
        const int arx   = (arow0 & 7) << 4;
        const int brow  = ((lid >> 4) << 3) + (lid & 7);
        const int bx    = ((lid >> 3) & 1) << 4;
        const int brx   = (lid & 7) << 4;

#pragma unroll 1
        for (int kc = 0; kc < NCH; ++kc) {
            const int s0 = kc % 3;
            BAR_SYNC(1 + s0);               // wait stage ready
            const uint32_t sA = sbase + SOFF_A + s0 * A_STAGE;
            const uint32_t sB = sbase + SOFF_B + s0 * B_STAGE;
#pragma unroll
            for (int ks = 0; ks < 4; ++ks) {
                const uint32_t kterm = (uint32_t)((ks * 32 + ax) ^ arx);
                uint32_t aH0[4], aL0[4], aH1[4], aL1[4];
                ldm4(aH0, sA + arow0 * 128 + kterm);
                ldm4(aL0, sA + A_PLANE + arow0 * 128 + kterm);
                ldm4(aH1, sA + (arow0 + 16) * 128 + kterm);
                ldm4(aL1, sA + A_PLANE + (arow0 + 16) * 128 + kterm);
#pragma unroll
                for (int nbi = 0; nbi < 2; ++nbi) {
                    uint32_t bH[4], bL[4];
                    const uint32_t baddr = sB + (nbase + nbi * 16 + brow) * 128
                                           + (uint32_t)((ks * 32 + bx) ^ brx);
                    ldm4(bH, baddr);
                    ldm4(bL, baddr + B_PLANE);
                    const int f = nbi * 2;
                    mma16816(accH[0][f],     aH0, bH[0], bH[1]);
                    mma16816(accH[1][f],     aH1, bH[0], bH[1]);
                    mma16816(accH[0][f + 1], aH0, bH[2], bH[3]);
                    mma16816(accH[1][f + 1], aH1, bH[2], bH[3]);
                    mma16816(accL[0][f],     aH0, bL[0], bL[1]);
                    mma16816(accL[1][f],     aH1, bL[0], bL[1]);
                    mma16816(accL[0][f + 1], aH0, bL[2], bL[3]);
                    mma16816(accL[1][f + 1], aH1, bL[2], bL[3]);
                    mma16816(accL[0][f],     aL0, bH[0], bH[1]);
                    mma16816(accL[1][f],     aL1, bH[0], bH[1]);
                    mma16816(accL[0][f + 1], aL0, bH[2], bH[3]);
                    mma16816(accL[1][f + 1], aL1, bH[2], bH[3]);
                }
            }
            BAR_ARRIVE(4 + s0);             // stage free
        }

        // combine planes
        float acc[2][4][4];
#pragma unroll
        for (int mt = 0; mt < 2; mt++)
#pragma unroll
            for (int f = 0; f < 4; f++)
#pragma unroll
                for (int c = 0; c < 4; c++)
                    acc[mt][f][c] = fmaf(accL[mt][f][c], LO_INV, accH[mt][f][c]);

        __syncthreads();    // join producers before reusing smem
        float* lg = (float*)smem;
        const int rq = lid >> 2;
        const int cq = (lid & 3) << 1;
#pragma unroll
        for (int mt = 0; mt < 2; mt++)
#pragma unroll
            for (int f = 0; f < 4; f++) {
                const int col = nbase + f * 8 + cq;
                const int r0  = mbase + mt * 16 + rq;
                *(float2*)(lg + r0 * 66 + col)       = make_float2(acc[mt][f][0], acc[mt][f][1]);
                *(float2*)(lg + (r0 + 8) * 66 + col) = make_float2(acc[mt][f][2], acc[mt][f][3]);
            }
    } else {
        // ================= PRODUCER: A+B in regs, STS-only hand-off =========
        const int pt = tid & 127;
        float4 areg[8];
        uint4  breg[8];

        // load chunk 0 into regs
#pragma unroll
        for (int i = 0; i < 8; i++) {
            const int q = pt + 128 * i;
            areg[i] = *(const float4*)(hblk + (size_t)(q >> 4) * DDIM + (q & 15) * 4);
        }
#pragma unroll
        for (int i = 0; i < 8; i++) breg[i] = gw[pt + 128 * i];

#pragma unroll 1
        for (int kc = 0; kc < NCH; ++kc) {
            const int w = kc % 3;
            if (kc >= 3) BAR_SYNC(4 + w);   // consumers freed stage w

            // STS A+B for chunk kc from regs
            char* ab = smem + SOFF_A + w * A_STAGE;
#pragma unroll
            for (int i = 0; i < 8; i++) {
                const int q = pt + 128 * i;
                uint32_t h0, l0, h1, l1;
                split2h(areg[i].x, areg[i].y, h0, l0);
                split2h(areg[i].z, areg[i].w, h1, l1);
                const int off = SWZ((q >> 4) * 128 + (q & 15) * 8);
                *(uint2*)(ab + off)           = make_uint2(h0, h1);
                *(uint2*)(ab + A_PLANE + off) = make_uint2(l0, l1);
            }
            char* bb = smem + SOFF_B + w * B_STAGE;
#pragma unroll
            for (int i = 0; i < 8; i++)
                *(uint4*)(bb + (pt + 128 * i) * 16) = breg[i];

            MEMBAR_CTA();
            BAR_ARRIVE(1 + w);              // stage w ready

            // load chunk kc+1 into regs (full chunk-time to return)
            if (kc + 1 < NCH) {
                const float* hp = hblk + (kc + 1) * KC;
#pragma unroll
                for (int i = 0; i < 8; i++) {
                    const int q = pt + 128 * i;
                    areg[i] = *(const float4*)(hp + (size_t)(q >> 4) * DDIM + (q & 15) * 4);
                }
                const uint4* gp = gw + (size_t)(kc + 1) * 1024;
#pragma unroll
                for (int i = 0; i < 8; i++) breg[i] = gp[pt + 128 * i];
            }
        }
        __syncthreads();    // join consumers before they reuse smem
    }

    __syncthreads();

    // ---- per-token softmax + top-2 ----
    float* lg = (float*)smem;
    if (tid < MROWS) {
        const float* row = lg + tid * 66;
        float v1 = -1e30f, v2 = -1e30f;
        int i1 = 0, i2 = 0;
#pragma unroll 8
        for (int e = 0; e < NEXP; ++e) {
            float l = row[e];
            if (l > v1) { v2 = v1; i2 = i1; v1 = l; i1 = e; }
            else if (l > v2) { v2 = l; i2 = e; }
        }
        float S = 0.f;
#pragma unroll 8
        for (int e = 0; e < NEXP; ++e) S += __expf(row[e] - v1);
        const float e1  = __expf(v2 - v1);
        const float den = 1.0f + e1 + 1e-9f * S;

        const size_t gt = (size_t)blockIdx.x * MROWS + tid;
        out[gt * 2 + 0] = 1.0f / den;
        out[gt * 2 + 1] = e1 / den;
        out[(size_t)2 * TTOK + gt * 2 + 0] = (float)i1;
        out[(size_t)2 * TTOK + gt * 2 + 1] = (float)i2;
    }
}

extern "C" void kernel_launch(void* const* d_in, const int* in_sizes, int n_in,
                              void* d_out, int out_size)
{
    const float* h = (const float*)d_in[0];
    const float* W = (const float*)d_in[1];
    float* out = (float*)d_out;

    split_w_kernel<<<512, 256>>>(W);

    static int smem_set = 0;
    if (!smem_set) {
        cudaFuncSetAttribute(gate_kernel, cudaFuncAttributeMaxDynamicSharedMemorySize,
                             SMEM_TOTAL);
        smem_set = 1;
    }
    gate_kernel<<<TTOK / MROWS, NTH, SMEM_TOTAL>>>(h, out);
}

// round 15
// speedup vs baseline: 1.0572x; 1.0572x over previous
#include <cuda_runtime.h>
#include <cuda_fp16.h>
#include <cstdint>

#define TTOK  16384
#define DDIM  4096
#define NEXP  64
#define MROWS 64                // tokens per CTA
#define KC    64                // k per chunk
#define NCH   (DDIM / KC)       // 64 chunks
#define NTH   256

#define SWZ(x) ((x) ^ (((x) >> 3) & 0x70))

// smem: 3-stage ring; per stage A 2 planes x 8KB + B 2 planes x 8KB
#define A_PLANE 8192
#define A_STAGE 16384
#define B_PLANE 8192
#define B_STAGE 16384
#define SOFF_A  0
#define SOFF_B  (3 * A_STAGE)               // 49152
#define SMEM_TOTAL (SOFF_B + 3 * B_STAGE)   // 98304

#define LO_SCALE   2048.0f
#define LO_INV     4.8828125e-4f            // 1/2048

// named barriers: ready[s] = 1+s (producer->consumer), free[s] = 4+s (consumer->producer)
#define BAR_SYNC(id)   asm volatile("bar.sync %0, 256;"   :: "r"(id) : "memory")
#define BAR_ARRIVE(id) asm volatile("bar.arrive %0, 256;" :: "r"(id) : "memory")
#define MEMBAR_CTA()   asm volatile("membar.cta;" ::: "memory")

// W pre-split planes, swizzled tile layout: [kc][plane(2)][2048 u32] (16KB/chunk)
__device__ __align__(16) uint32_t gWs[NCH * 2 * 2048];

// ---- fp16 2-way split of two floats; lo pre-scaled by 2048 ----
__device__ __forceinline__ void split2h(float x0, float x1,
                                        uint32_t& whi, uint32_t& wlo) {
    __half2 hh = __float22half2_rn(make_float2(x0, x1));
    float2 back = __half22float2(hh);
    float r0 = (x0 - back.x) * LO_SCALE;
    float r1 = (x1 - back.y) * LO_SCALE;
    __half2 ll = __float22half2_rn(make_float2(r0, r1));
    whi = *(uint32_t*)&hh;
    wlo = *(uint32_t*)&ll;
}

__device__ __forceinline__ uint32_t s2u(const void* p) {
    uint32_t a;
    asm("{ .reg .u64 t; cvta.to.shared.u64 t, %1; cvt.u32.u64 %0, t; }" : "=r"(a) : "l"(p));
    return a;
}

__device__ __forceinline__ void ldm4(uint32_t* r, uint32_t addr) {
    asm volatile("ldmatrix.sync.aligned.m8n8.x4.shared.b16 {%0,%1,%2,%3}, [%4];"
                 : "=r"(r[0]), "=r"(r[1]), "=r"(r[2]), "=r"(r[3]) : "r"(addr));
}

__device__ __forceinline__ void mma16816(float* d, const uint32_t* a,
                                         uint32_t b0, uint32_t b1) {
    asm volatile("mma.sync.aligned.m16n8k16.row.col.f32.f16.f16.f32 "
                 "{%0,%1,%2,%3}, {%4,%5,%6,%7}, {%8,%9}, {%0,%1,%2,%3};"
                 : "+f"(d[0]), "+f"(d[1]), "+f"(d[2]), "+f"(d[3])
                 : "r"(a[0]), "r"(a[1]), "r"(a[2]), "r"(a[3]), "r"(b0), "r"(b1));
}

#define CP16(s, g) \
    asm volatile("cp.async.cg.shared.global [%0], [%1], 16;" :: "r"(s), "l"(g))
#define CP_COMMIT()  asm volatile("cp.async.commit_group;" ::: "memory")
#define CP_WAIT(n)   asm volatile("cp.async.wait_group %0;" :: "n"(n) : "memory")

// ---- kernel 0: split W once into swizzled fp16 plane tiles ----
__global__ __launch_bounds__(256)
void split_w_kernel(const float* __restrict__ W) {
    const int j = blockIdx.x * 256 + threadIdx.x;   // pair index, 0..131071
    const int e  = j >> 11;                          // expert 0..63
    const int k0 = (j & 2047) << 1;                  // even k
    float x0 = W[e * DDIM + k0];
    float x1 = W[e * DDIM + k0 + 1];
    uint32_t whi, wlo;
    split2h(x0, x1, whi, wlo);
    const int kc  = k0 >> 6;
    const int off = SWZ(e * 128 + (k0 & 63) * 2) >> 2;   // u32 index in tile
    gWs[(kc * 2 + 0) * 2048 + off] = whi;
    gWs[(kc * 2 + 1) * 2048 + off] = wlo;
}

// ---- main: warp-specialized; producer holds a 2-chunk standing lead ----
__global__ __launch_bounds__(NTH, 2)
void gate_kernel(const float* __restrict__ h, float* __restrict__ out)
{
    extern __shared__ __align__(16) char smem[];
    const uint32_t sbase = s2u(smem);
    const int tid = threadIdx.x;
    const int wid = tid >> 5;
    const int lid = tid & 31;

    const float* hblk = h + (size_t)blockIdx.x * MROWS * DDIM;
    const uint4* gw = (const uint4*)gWs;   // 1024 uint4 per chunk

    const bool is_prod = (wid >= 4);

    if (!is_prod) {
        // ================= CONSUMER: pure ldmatrix + MMA =================
        float accH[2][4][4], accL[2][4][4];
#pragma unroll
        for (int mt = 0; mt < 2; mt++)
#pragma unroll
            for (int f = 0; f < 4; f++)
#pragma unroll
                for (int c = 0; c < 4; c++) { accH[mt][f][c] = 0.f; accL[mt][f][c] = 0.f; }

        const int mbase = (wid & 1) << 5;
        const int nbase = ((wid >> 1) & 1) << 5;
        const int arow0 = mbase + (lid & 15);
        const int ax    = (lid >> 4) << 4;
        const int arx   = (arow0 & 7) << 4;
        const int brow  = ((lid >> 4) << 3) + (lid & 7);
        const int bx    = ((lid >> 3) & 1) << 4;
        const int brx   = (lid & 7) << 4;

#pragma unroll 1
        for (int kc = 0; kc < NCH; ++kc) {
            const int s0 = kc % 3;
            BAR_SYNC(1 + s0);               // wait stage ready
            const uint32_t sA = sbase + SOFF_A + s0 * A_STAGE;
            const uint32_t sB = sbase + SOFF_B + s0 * B_STAGE;
#pragma unroll
            for (int ks = 0; ks < 4; ++ks) {
                const uint32_t kterm = (uint32_t)((ks * 32 + ax) ^ arx);
                uint32_t aH0[4], aL0[4], aH1[4], aL1[4];
                ldm4(aH0, sA + arow0 * 128 + kterm);
                ldm4(aL0, sA + A_PLANE + arow0 * 128 + kterm);
                ldm4(aH1, sA + (arow0 + 16) * 128 + kterm);
                ldm4(aL1, sA + A_PLANE + (arow0 + 16) * 128 + kterm);
#pragma unroll
                for (int nbi = 0; nbi < 2; ++nbi) {
                    uint32_t bH[4], bL[4];
                    const uint32_t baddr = sB + (nbase + nbi * 16 + brow) * 128
                                           + (uint32_t)((ks * 32 + bx) ^ brx);
                    ldm4(bH, baddr);
                    ldm4(bL, baddr + B_PLANE);
                    const int f = nbi * 2;
                    mma16816(accH[0][f],     aH0, bH[0], bH[1]);
                    mma16816(accH[1][f],     aH1, bH[0], bH[1]);
                    mma16816(accH[0][f + 1], aH0, bH[2], bH[3]);
                    mma16816(accH[1][f + 1], aH1, bH[2], bH[3]);
                    mma16816(accL[0][f],     aH0, bL[0], bL[1]);
                    mma16816(accL[1][f],     aH1, bL[0], bL[1]);
                    mma16816(accL[0][f + 1], aH0, bL[2], bL[3]);
                    mma16816(accL[1][f + 1], aH1, bL[2], bL[3]);
                    mma16816(accL[0][f],     aL0, bH[0], bH[1]);
                    mma16816(accL[1][f],     aL1, bH[0], bH[1]);
                    mma16816(accL[0][f + 1], aL0, bH[2], bH[3]);
                    mma16816(accL[1][f + 1], aL1, bH[2], bH[3]);
                }
            }
            BAR_ARRIVE(4 + s0);             // stage free
        }

        // combine planes
        float acc[2][4][4];
#pragma unroll
        for (int mt = 0; mt < 2; mt++)
#pragma unroll
            for (int f = 0; f < 4; f++)
#pragma unroll
                for (int c = 0; c < 4; c++)
                    acc[mt][f][c] = fmaf(accL[mt][f][c], LO_INV, accH[mt][f][c]);

        __syncthreads();    // join producers before reusing smem
        float* lg = (float*)smem;
        const int rq = lid >> 2;
        const int cq = (lid & 3) << 1;
#pragma unroll
        for (int mt = 0; mt < 2; mt++)
#pragma unroll
            for (int f = 0; f < 4; f++) {
                const int col = nbase + f * 8 + cq;
                const int r0  = mbase + mt * 16 + rq;
                *(float2*)(lg + r0 * 66 + col)       = make_float2(acc[mt][f][0], acc[mt][f][1]);
                *(float2*)(lg + (r0 + 8) * 66 + col) = make_float2(acc[mt][f][2], acc[mt][f][3]);
            }
    } else {
        // ================= PRODUCER: fills 3 stages, stays 2 ahead =========
        const int pt = tid & 127;
        float4 areg[8];

        // prologue: chunks 0..2 -> stages 0..2
#pragma unroll 1
        for (int c = 0; c < 3; ++c) {
            const float* hp = hblk + c * KC;
#pragma unroll
            for (int i = 0; i < 8; i++) {
                const int q = pt + 128 * i;
                areg[i] = *(const float4*)(hp + (size_t)(q >> 4) * DDIM + (q & 15) * 4);
            }
            char* ab = smem + SOFF_A + c * A_STAGE;
#pragma unroll
            for (int i = 0; i < 8; i++) {
                const int q = pt + 128 * i;
                uint32_t h0, l0, h1, l1;
                split2h(areg[i].x, areg[i].y, h0, l0);
                split2h(areg[i].z, areg[i].w, h1, l1);
                const int off = SWZ((q >> 4) * 128 + (q & 15) * 8);
                *(uint2*)(ab + off)           = make_uint2(h0, h1);
                *(uint2*)(ab + A_PLANE + off) = make_uint2(l0, l1);
            }
            const uint4* gp = gw + (size_t)c * 1024;
            const uint32_t sBn = sbase + SOFF_B + c * B_STAGE;
#pragma unroll
            for (int i = 0; i < 8; i++) {
                const int idx = pt + 128 * i;
                CP16(sBn + idx * 16, gp + idx);
            }
            CP_COMMIT();
        }
        // A chunk 3 -> regs for first loop iteration
        {
            const float* hp = hblk + 3 * KC;
#pragma unroll
            for (int i = 0; i < 8; i++) {
                const int q = pt + 128 * i;
                areg[i] = *(const float4*)(hp + (size_t)(q >> 4) * DDIM + (q & 15) * 4);
            }
        }
        CP_WAIT(0);
        MEMBAR_CTA();
        BAR_ARRIVE(1);
        BAR_ARRIVE(2);
        BAR_ARRIVE(3);

        // steady state: at iteration kc produce chunk kc+3 into stage kc%3
#pragma unroll 1
        for (int kc = 0; kc + 3 < NCH; ++kc) {
            const int w = kc % 3;
            BAR_SYNC(4 + w);                // consumers freed stage w (chunk kc)

            // STS A chunk kc+3 from regs
            char* ab = smem + SOFF_A + w * A_STAGE;
#pragma unroll
            for (int i = 0; i < 8; i++) {
                const int q = pt + 128 * i;
                uint32_t h0, l0, h1, l1;
                split2h(areg[i].x, areg[i].y, h0, l0);
                split2h(areg[i].z, areg[i].w, h1, l1);
                const int off = SWZ((q >> 4) * 128 + (q & 15) * 8);
                *(uint2*)(ab + off)           = make_uint2(h0, h1);
                *(uint2*)(ab + A_PLANE + off) = make_uint2(l0, l1);
            }
            // B chunk kc+3 via cp.async into stage w
            const uint4* gp = gw + (size_t)(kc + 3) * 1024;
            const uint32_t sBn = sbase + SOFF_B + w * B_STAGE;
#pragma unroll
            for (int i = 0; i < 8; i++) {
                const int idx = pt + 128 * i;
                CP16(sBn + idx * 16, gp + idx);
            }
            CP_COMMIT();
            // LDG A chunk kc+4 -> regs
            if (kc + 4 < NCH) {
                const float* hp = hblk + (kc + 4) * KC;
#pragma unroll
                for (int i = 0; i < 8; i++) {
                    const int q = pt + 128 * i;
                    areg[i] = *(const float4*)(hp + (size_t)(q >> 4) * DDIM + (q & 15) * 4);
                }
            }
            CP_WAIT(0);
            MEMBAR_CTA();
            BAR_ARRIVE(1 + w);              // stage w ready (chunk kc+3)
        }
        __syncthreads();    // join consumers before they reuse smem
    }

    __syncthreads();

    // ---- per-token softmax + top-2 ----
    float* lg = (float*)smem;
    if (tid < MROWS) {
        const float* row = lg + tid * 66;
        float v1 = -1e30f, v2 = -1e30f;
        int i1 = 0, i2 = 0;
#pragma unroll 8
        for (int e = 0; e < NEXP; ++e) {
            float l = row[e];
            if (l > v1) { v2 = v1; i2 = i1; v1 = l; i1 = e; }
            else if (l > v2) { v2 = l; i2 = e; }
        }
        float S = 0.f;
#pragma unroll 8
        for (int e = 0; e < NEXP; ++e) S += __expf(row[e] - v1);
        const float e1  = __expf(v2 - v1);
        const float den = 1.0f + e1 + 1e-9f * S;

        const size_t gt = (size_t)blockIdx.x * MROWS + tid;
        out[gt * 2 + 0] = 1.0f / den;
        out[gt * 2 + 1] = e1 / den;
        out[(size_t)2 * TTOK + gt * 2 + 0] = (float)i1;
        out[(size_t)2 * TTOK + gt * 2 + 1] = (float)i2;
    }
}

extern "C" void kernel_launch(void* const* d_in, const int* in_sizes, int n_in,
                              void* d_out, int out_size)
{
    const float* h = (const float*)d_in[0];
    const float* W = (const float*)d_in[1];
    float* out = (float*)d_out;

    split_w_kernel<<<512, 256>>>(W);

    static int smem_set = 0;
    if (!smem_set) {
        cudaFuncSetAttribute(gate_kernel, cudaFuncAttributeMaxDynamicSharedMemorySize,
                             SMEM_TOTAL);
        smem_set = 1;
    }
    gate_kernel<<<TTOK / MROWS, NTH, SMEM_TOTAL>>>(h, out);
}

// round 17
// speedup vs baseline: 1.0712x; 1.0133x over previous
#include <cuda_runtime.h>
#include <cuda_fp16.h>
#include <cstdint>

#define TTOK  16384
#define DDIM  4096
#define NEXP  64
#define MROWS 64                // tokens per CTA
#define KC    64                // k per chunk
#define NCH   (DDIM / KC)       // 64 chunks
#define NTH   256

#define SWZ(x) ((x) ^ (((x) >> 3) & 0x70))

// smem: 3-stage ring; per stage A 2 planes x 8KB + B 2 planes x 8KB
#define A_PLANE 8192
#define A_STAGE 16384
#define B_PLANE 8192
#define B_STAGE 16384
#define SOFF_A  0
#define SOFF_B  (3 * A_STAGE)               // 49152
#define SMEM_TOTAL (SOFF_B + 3 * B_STAGE)   // 98304

#define LO_SCALE   2048.0f
#define LO_INV     4.8828125e-4f            // 1/2048

// named barriers: ready[s] = 1+s (producer->consumer), free[s] = 4+s (consumer->producer)
#define BAR_SYNC(id)   asm volatile("bar.sync %0, 256;"   :: "r"(id) : "memory")
#define BAR_ARRIVE(id) asm volatile("bar.arrive %0, 256;" :: "r"(id) : "memory")
#define MEMBAR_CTA()   asm volatile("membar.cta;" ::: "memory")

// W pre-split planes, swizzled tile layout: [kc][plane(2)][2048 u32] (16KB/chunk)
__device__ __align__(16) uint32_t gWs[NCH * 2 * 2048];

// ---- fp16 2-way split of two floats; lo pre-scaled by 2048 ----
__device__ __forceinline__ void split2h(float x0, float x1,
                                        uint32_t& whi, uint32_t& wlo) {
    __half2 hh = __float22half2_rn(make_float2(x0, x1));
    float2 back = __half22float2(hh);
    float r0 = (x0 - back.x) * LO_SCALE;
    float r1 = (x1 - back.y) * LO_SCALE;
    __half2 ll = __float22half2_rn(make_float2(r0, r1));
    whi = *(uint32_t*)&hh;
    wlo = *(uint32_t*)&ll;
}

__device__ __forceinline__ uint32_t s2u(const void* p) {
    uint32_t a;
    asm("{ .reg .u64 t; cvta.to.shared.u64 t, %1; cvt.u32.u64 %0, t; }" : "=r"(a) : "l"(p));
    return a;
}

__device__ __forceinline__ void ldm4(uint32_t* r, uint32_t addr) {
    asm volatile("ldmatrix.sync.aligned.m8n8.x4.shared.b16 {%0,%1,%2,%3}, [%4];"
                 : "=r"(r[0]), "=r"(r[1]), "=r"(r[2]), "=r"(r[3]) : "r"(addr));
}

__device__ __forceinline__ void mma16816(float* d, const uint32_t* a,
                                         uint32_t b0, uint32_t b1) {
    asm volatile("mma.sync.aligned.m16n8k16.row.col.f32.f16.f16.f32 "
                 "{%0,%1,%2,%3}, {%4,%5,%6,%7}, {%8,%9}, {%0,%1,%2,%3};"
                 : "+f"(d[0]), "+f"(d[1]), "+f"(d[2]), "+f"(d[3])
                 : "r"(a[0]), "r"(a[1]), "r"(a[2]), "r"(a[3]), "r"(b0), "r"(b1));
}

#define CP16(s, g) \
    asm volatile("cp.async.cg.shared.global [%0], [%1], 16;" :: "r"(s), "l"(g))
#define CP_COMMIT()  asm volatile("cp.async.commit_group;" ::: "memory")
#define CP_WAIT(n)   asm volatile("cp.async.wait_group %0;" :: "n"(n) : "memory")

// ---- kernel 0: split W once into swizzled fp16 plane tiles ----
__global__ __launch_bounds__(256)
void split_w_kernel(const float* __restrict__ W) {
    const int j = blockIdx.x * 256 + threadIdx.x;   // pair index, 0..131071
    const int e  = j >> 11;                          // expert 0..63
    const int k0 = (j & 2047) << 1;                  // even k
    float x0 = W[e * DDIM + k0];
    float x1 = W[e * DDIM + k0 + 1];
    uint32_t whi, wlo;
    split2h(x0, x1, whi, wlo);
    const int kc  = k0 >> 6;
    const int off = SWZ(e * 128 + (k0 & 63) * 2) >> 2;   // u32 index in tile
    gWs[(kc * 2 + 0) * 2048 + off] = whi;
    gWs[(kc * 2 + 1) * 2048 + off] = wlo;
}

// ---- main: warp-specialized, reordered mma schedule + early stage-free ----
__global__ __launch_bounds__(NTH, 2)
void gate_kernel(const float* __restrict__ h, float* __restrict__ out)
{
    extern __shared__ __align__(16) char smem[];
    const uint32_t sbase = s2u(smem);
    const int tid = threadIdx.x;
    const int wid = tid >> 5;
    const int lid = tid & 31;

    const float* hblk = h + (size_t)blockIdx.x * MROWS * DDIM;
    const uint4* gw = (const uint4*)gWs;   // 1024 uint4 per chunk

    const bool is_prod = (wid >= 4);

    if (!is_prod) {
        // ================= CONSUMER: pure ldmatrix + MMA =================
        float accH[2][4][4], accL[2][4][4];
#pragma unroll
        for (int mt = 0; mt < 2; mt++)
#pragma unroll
            for (int f = 0; f < 4; f++)
#pragma unroll
                for (int c = 0; c < 4; c++) { accH[mt][f][c] = 0.f; accL[mt][f][c] = 0.f; }

        const int mbase = (wid & 1) << 5;
        const int nbase = ((wid >> 1) & 1) << 5;
        const int arow0 = mbase + (lid & 15);
        const int ax    = (lid >> 4) << 4;
        const int arx   = (arow0 & 7) << 4;
        const int brow  = ((lid >> 4) << 3) + (lid & 7);
        const int bx    = ((lid >> 3) & 1) << 4;
        const int brx   = (lid & 7) << 4;

#pragma unroll 1
        for (int kc = 0; kc < NCH; ++kc) {
            const int s0 = kc % 3;
            BAR_SYNC(1 + s0);               // wait stage ready
            const uint32_t sA = sbase + SOFF_A + s0 * A_STAGE;
            const uint32_t sB = sbase + SOFF_B + s0 * B_STAGE;
#pragma unroll
            for (int ks = 0; ks < 4; ++ks) {
                const uint32_t kterm = (uint32_t)((ks * 32 + ax) ^ arx);
                const uint32_t bterm = (uint32_t)((ks * 32 + bx) ^ brx);
                const uint32_t ba0 = sB + (nbase + brow) * 128 + bterm;
                const uint32_t ba1 = sB + (nbase + 16 + brow) * 128 + bterm;

                // all loads hoisted: latency overlaps the mma stream
                uint32_t aH0[4], aH1[4], aL0[4], aL1[4];
                uint32_t bH0[4], bH1[4], bL0[4], bL1[4];
                ldm4(aH0, sA + arow0 * 128 + kterm);
                ldm4(aH1, sA + (arow0 + 16) * 128 + kterm);
                ldm4(bH0, ba0);
                ldm4(bH1, ba1);
                ldm4(bL0, ba0 + B_PLANE);
                ldm4(bL1, ba1 + B_PLANE);
                ldm4(aL0, sA + A_PLANE + arow0 * 128 + kterm);
                ldm4(aL1, sA + A_PLANE + (arow0 + 16) * 128 + kterm);

                // last smem reads of this stage done -> free it early
                if (ks == 3) BAR_ARRIVE(4 + s0);

                // block 1: hh -> accH (8 independent)
                mma16816(accH[0][0], aH0, bH0[0], bH0[1]);
                mma16816(accH[1][0], aH1, bH0[0], bH0[1]);
                mma16816(accH[0][1], aH0, bH0[2], bH0[3]);
                mma16816(accH[1][1], aH1, bH0[2], bH0[3]);
                mma16816(accH[0][2], aH0, bH1[0], bH1[1]);
                mma16816(accH[1][2], aH1, bH1[0], bH1[1]);
                mma16816(accH[0][3], aH0, bH1[2], bH1[3]);
                mma16816(accH[1][3], aH1, bH1[2], bH1[3]);
                // block 2: hi_h x lo_W -> accL
                mma16816(accL[0][0], aH0, bL0[0], bL0[1]);
                mma16816(accL[1][0], aH1, bL0[0], bL0[1]);
                mma16816(accL[0][1], aH0, bL0[2], bL0[3]);
                mma16816(accL[1][1], aH1, bL0[2], bL0[3]);
                mma16816(accL[0][2], aH0, bL1[0], bL1[1]);
                mma16816(accL[1][2], aH1, bL1[0], bL1[1]);
                mma16816(accL[0][3], aH0, bL1[2], bL1[3]);
                mma16816(accL[1][3], aH1, bL1[2], bL1[3]);
                // block 3: lo_h x hi_W -> accL (distance 8 from block 2 writes)
                mma16816(accL[0][0], aL0, bH0[0], bH0[1]);
                mma16816(accL[1][0], aL1, bH0[0], bH0[1]);
                mma16816(accL[0][1], aL0, bH0[2], bH0[3]);
                mma16816(accL[1][1], aL1, bH0[2], bH0[3]);
                mma16816(accL[0][2], aL0, bH1[0], bH1[1]);
                mma16816(accL[1][2], aL1, bH1[0], bH1[1]);
                mma16816(accL[0][3], aL0, bH1[2], bH1[3]);
                mma16816(accL[1][3], aL1, bH1[2], bH1[3]);
            }
        }

        // combine planes
        float acc[2][4][4];
#pragma unroll
        for (int mt = 0; mt < 2; mt++)
#pragma unroll
            for (int f = 0; f < 4; f++)
#pragma unroll
                for (int c = 0; c < 4; c++)
                    acc[mt][f][c] = fmaf(accL[mt][f][c], LO_INV, accH[mt][f][c]);

        __syncthreads();    // join producers before reusing smem
        float* lg = (float*)smem;
        const int rq = lid >> 2;
        const int cq = (lid & 3) << 1;
#pragma unroll
        for (int mt = 0; mt < 2; mt++)
#pragma unroll
            for (int f = 0; f < 4; f++) {
                const int col = nbase + ((f >> 1) << 4) + ((f & 1) << 3) + cq;
                const int r0  = mbase + mt * 16 + rq;
                *(float2*)(lg + r0 * 66 + col)       = make_float2(acc[mt][f][0], acc[mt][f][1]);
                *(float2*)(lg + (r0 + 8) * 66 + col) = make_float2(acc[mt][f][2], acc[mt][f][3]);
            }
    } else {
        // ================= PRODUCER (R13 form) =================
        const int pt = tid & 127;
        float4 areg[8];

        // prologue: chunk 0 -> regs -> stage 0 (A STS + B cp.async)
#pragma unroll
        for (int i = 0; i < 8; i++) {
            const int q = pt + 128 * i;
            areg[i] = *(const float4*)(hblk + (size_t)(q >> 4) * DDIM + (q & 15) * 4);
        }
        {
            char* ab = smem + SOFF_A;
#pragma unroll
            for (int i = 0; i < 8; i++) {
                const int q = pt + 128 * i;
                uint32_t h0, l0, h1, l1;
                split2h(areg[i].x, areg[i].y, h0, l0);
                split2h(areg[i].z, areg[i].w, h1, l1);
                const int off = SWZ((q >> 4) * 128 + (q & 15) * 8);
                *(uint2*)(ab + off)           = make_uint2(h0, h1);
                *(uint2*)(ab + A_PLANE + off) = make_uint2(l0, l1);
            }
#pragma unroll
            for (int i = 0; i < 8; i++) {
                const int idx = pt + 128 * i;
                CP16(sbase + SOFF_B + idx * 16, gw + idx);
            }
            CP_COMMIT();
            // chunk 1 -> regs while cp.async flies
#pragma unroll
            for (int i = 0; i < 8; i++) {
                const int q = pt + 128 * i;
                areg[i] = *(const float4*)(hblk + (size_t)(q >> 4) * DDIM + KC + (q & 15) * 4);
            }
            CP_WAIT(0);
            MEMBAR_CTA();
            BAR_ARRIVE(1 + 0);              // stage 0 ready
        }

#pragma unroll 1
        for (int kc = 0; kc < NCH; ++kc) {
            if (kc + 1 < NCH) {
                const int w = (kc + 1) % 3;
                if (kc + 1 >= 3) BAR_SYNC(4 + w);   // consumers freed stage w
                // STS A chunk kc+1 from regs
                char* ab = smem + SOFF_A + w * A_STAGE;
#pragma unroll
                for (int i = 0; i < 8; i++) {
                    const int q = pt + 128 * i;
                    uint32_t h0, l0, h1, l1;
                    split2h(areg[i].x, areg[i].y, h0, l0);
                    split2h(areg[i].z, areg[i].w, h1, l1);
                    const int off = SWZ((q >> 4) * 128 + (q & 15) * 8);
                    *(uint2*)(ab + off)           = make_uint2(h0, h1);
                    *(uint2*)(ab + A_PLANE + off) = make_uint2(l0, l1);
                }
                // B chunk kc+1 via cp.async into same stage
                const uint4* gp = gw + (size_t)(kc + 1) * 1024;
                const uint32_t sBn = sbase + SOFF_B + w * B_STAGE;
#pragma unroll
                for (int i = 0; i < 8; i++) {
                    const int idx = pt + 128 * i;
                    CP16(sBn + idx * 16, gp + idx);
                }
                CP_COMMIT();
                // LDG chunk kc+2 -> regs (for next iteration's STS)
                if (kc + 2 < NCH) {
                    const float* hp = hblk + (kc + 2) * KC;
#pragma unroll
                    for (int i = 0; i < 8; i++) {
                        const int q = pt + 128 * i;
                        areg[i] = *(const float4*)(hp + (size_t)(q >> 4) * DDIM + (q & 15) * 4);
                    }
                }
                CP_WAIT(0);
                MEMBAR_CTA();
                BAR_ARRIVE(1 + w);          // stage w ready
            }
        }
        __syncthreads();    // join consumers before they reuse smem
    }

    __syncthreads();

    // ---- per-token softmax + top-2 ----
    float* lg = (float*)smem;
    if (tid < MROWS) {
        const float* row = lg + tid * 66;
        float v1 = -1e30f, v2 = -1e30f;
        int i1 = 0, i2 = 0;
#pragma unroll 8
        for (int e = 0; e < NEXP; ++e) {
            float l = row[e];
            if (l > v1) { v2 = v1; i2 = i1; v1 = l; i1 = e; }
            else if (l > v2) { v2 = l; i2 = e; }
        }
        float S = 0.f;
#pragma unroll 8
        for (int e = 0; e < NEXP; ++e) S += __expf(row[e] - v1);
        const float e1  = __expf(v2 - v1);
        const float den = 1.0f + e1 + 1e-9f * S;

        const size_t gt = (size_t)blockIdx.x * MROWS + tid;
        out[gt * 2 + 0] = 1.0f / den;
        out[gt * 2 + 1] = e1 / den;
        out[(size_t)2 * TTOK + gt * 2 + 0] = (float)i1;
        out[(size_t)2 * TTOK + gt * 2 + 1] = (float)i2;
    }
}

extern "C" void kernel_launch(void* const* d_in, const int* in_sizes, int n_in,
                              void* d_out, int out_size)
{
    const float* h = (const float*)d_in[0];
    const float* W = (const float*)d_in[1];
    float* out = (float*)d_out;

    split_w_kernel<<<512, 256>>>(W);

    static int smem_set = 0;
    if (!smem_set) {
        cudaFuncSetAttribute(gate_kernel, cudaFuncAttributeMaxDynamicSharedMemorySize,
                             SMEM_TOTAL);
        smem_set = 1;
    }
    gate_kernel<<<TTOK / MROWS, NTH, SMEM_TOTAL>>>(h, out);
}